// round 16
// baseline (speedup 1.0000x reference)
#include <cuda_runtime.h>
#include <cuda_bf16.h>
#include <math.h>
#include <stdint.h>

#define NN   1024
#define SS   64
#define DD   256
#define HH   4
#define HDIM 64
#define EE   4096
#define ROWS (NN*SS)   // 65536

// -------- scratch (allocation-free: device globals) --------
__device__ __nv_bfloat16 g_xn_hi[ROWS*DD];
__device__ __nv_bfloat16 g_xn_lo[ROWS*DD];
__device__ __nv_bfloat16 g_q_hi [ROWS*DD];   // pre-scaled by 1/8
__device__ __nv_bfloat16 g_q_lo [ROWS*DD];
__device__ __nv_bfloat16 g_k_hi [ROWS*DD];
__device__ __nv_bfloat16 g_k_lo [ROWS*DD];
__device__ __nv_bfloat16 g_v_hi [ROWS*DD];
__device__ __nv_bfloat16 g_v_lo [ROWS*DD];
__device__ float g_ctx[ROWS*DD];
__device__ __nv_bfloat16 g_wt_hi[4*DD*DD];   // transposed weights [n][k] (q,k,v,o)
__device__ __nv_bfloat16 g_wt_lo[4*DD*DD];
// CSR-by-dst edge structures
__device__ int g_srcv[EE];
__device__ int g_dstv[EE];
__device__ int g_ettv[EE];
__device__ int g_deg[NN];
__device__ int g_off[NN+1];
__device__ int g_elist[EE];

// ================= MMA / ldmatrix helpers =================
__device__ __forceinline__ void mma_bf16(float c[4],
    uint32_t a0, uint32_t a1, uint32_t a2, uint32_t a3, uint32_t b0, uint32_t b1) {
    asm volatile(
        "mma.sync.aligned.m16n8k16.row.col.f32.bf16.bf16.f32 "
        "{%0,%1,%2,%3}, {%4,%5,%6,%7}, {%8,%9}, {%0,%1,%2,%3};"
        : "+f"(c[0]), "+f"(c[1]), "+f"(c[2]), "+f"(c[3])
        : "r"(a0), "r"(a1), "r"(a2), "r"(a3), "r"(b0), "r"(b1));
}
__device__ __forceinline__ void ldsm4(uint32_t a, uint32_t& r0, uint32_t& r1,
                                      uint32_t& r2, uint32_t& r3) {
    asm volatile("ldmatrix.sync.aligned.m8n8.x4.shared.b16 {%0,%1,%2,%3}, [%4];"
        : "=r"(r0), "=r"(r1), "=r"(r2), "=r"(r3) : "r"(a));
}
__device__ __forceinline__ void ldsm4t(uint32_t a, uint32_t& r0, uint32_t& r1,
                                       uint32_t& r2, uint32_t& r3) {
    asm volatile("ldmatrix.sync.aligned.m8n8.x4.trans.shared.b16 {%0,%1,%2,%3}, [%4];"
        : "=r"(r0), "=r"(r1), "=r"(r2), "=r"(r3) : "r"(a));
}
__device__ __forceinline__ uint32_t smem_u32(const void* p) {
    uint32_t r;
    asm("{ .reg .u64 t; cvta.to.shared.u64 t, %1; cvt.u32.u64 %0, t; }" : "=r"(r) : "l"(p));
    return r;
}
__device__ __forceinline__ uint32_t packbf(float x, float y) {
    __nv_bfloat162 t = __floats2bfloat162_rn(x, y);
    return *(uint32_t*)&t;
}
__device__ __forceinline__ float bflo(float x) {
    return x - __bfloat162float(__float2bfloat16(x));
}
__device__ __forceinline__ void split4(float4 v, uint32_t& hi2a, uint32_t& hi2b,
                                       uint32_t& lo2a, uint32_t& lo2b) {
    hi2a = packbf(v.x, v.y); hi2b = packbf(v.z, v.w);
    lo2a = packbf(bflo(v.x), bflo(v.y)); lo2b = packbf(bflo(v.z), bflo(v.w));
}

// ---------------- CSR build (by dst) ----------------
__global__ __launch_bounds__(256) void edges0_kernel() {
    int i = blockIdx.x * 256 + threadIdx.x;
    if (i < NN) g_deg[i] = 0;
}
__global__ __launch_bounds__(256) void edges1_kernel(
    const long long* __restrict__ ei, const long long* __restrict__ et) {
    int e = blockIdx.x * 256 + threadIdx.x;
    if (e >= EE) return;
    bool is64 = true;
    #pragma unroll
    for (int i = 0; i < 16; i++) {
        long long v = ei[i];
        if (v < 0 || v >= NN) { is64 = false; break; }
    }
    const int* ei32 = (const int*)ei;
    const int* et32 = (const int*)et;
    int src = is64 ? (int)ei[e]      : ei32[e];
    int dst = is64 ? (int)ei[EE + e] : ei32[EE + e];
    int tt  = is64 ? (int)et[e]      : et32[e];
    g_srcv[e] = src;
    g_dstv[e] = dst;
    g_ettv[e] = tt;
    atomicAdd(&g_deg[dst], 1);
}
// single block: scan offsets + stable fill by dst
__global__ __launch_bounds__(1024) void edges2_kernel() {
    __shared__ int sdeg[1024];
    __shared__ int sdst[2048];
    int s = threadIdx.x;
    int v = g_deg[s];
    sdeg[s] = v;
    __syncthreads();
    #pragma unroll
    for (int off = 1; off < 1024; off <<= 1) {
        int t = (s >= off) ? sdeg[s - off] : 0;
        __syncthreads();
        sdeg[s] += t;
        __syncthreads();
    }
    int excl = sdeg[s] - v;
    g_off[s] = excl;
    if (s == 1023) g_off[1024] = sdeg[1023];
    int c = excl;
    for (int base = 0; base < EE; base += 2048) {
        __syncthreads();
        for (int j = s; j < 2048; j += 1024) sdst[j] = g_dstv[base + j];
        __syncthreads();
        for (int j = 0; j < 2048; j++)
            if (sdst[j] == s) g_elist[c++] = base + j;
    }
}

// ---------------- zero the context accumulator (mask-skipped) ----------------
__global__ __launch_bounds__(256) void zero_ctx_kernel(const float* __restrict__ masks) {
    int gid = blockIdx.x * 256 + threadIdx.x;
    int row = gid >> 2;
    if (masks[row & ~15] <= 0.f) return;
    float4* p = (float4*)(g_ctx + (size_t)row * DD) + (gid & 3) * 16;
    float4 z = make_float4(0.f, 0.f, 0.f, 0.f);
    #pragma unroll
    for (int i = 0; i < 16; i++) p[i] = z;
}

// ---------------- LayerNorm -> bf16 hi/lo split (mask-skipped) ----------------
__global__ __launch_bounds__(256) void ln_kernel(
    const float* __restrict__ x, const float* __restrict__ w, const float* __restrict__ b,
    const float* __restrict__ masks) {
    int row  = blockIdx.x * 8 + (threadIdx.x >> 5);
    int lane = threadIdx.x & 31;
    if (masks[row & ~15] <= 0.f) return;
    const float4* xr = (const float4*)(x + (size_t)row * DD);
    float4 v0 = xr[lane];
    float4 v1 = xr[32 + lane];
    float s = v0.x + v0.y + v0.z + v0.w + v1.x + v1.y + v1.z + v1.w;
    #pragma unroll
    for (int o = 16; o; o >>= 1) s += __shfl_xor_sync(0xffffffffu, s, o);
    float mu = s * (1.0f / DD);
    float d0 = v0.x - mu, d1 = v0.y - mu, d2 = v0.z - mu, d3 = v0.w - mu;
    float d4 = v1.x - mu, d5 = v1.y - mu, d6 = v1.z - mu, d7 = v1.w - mu;
    float ss = d0*d0 + d1*d1 + d2*d2 + d3*d3 + d4*d4 + d5*d5 + d6*d6 + d7*d7;
    #pragma unroll
    for (int o = 16; o; o >>= 1) ss += __shfl_xor_sync(0xffffffffu, ss, o);
    float inv = rsqrtf(ss * (1.0f / DD) + 1e-5f);
    float4 w0 = ((const float4*)w)[lane], w1 = ((const float4*)w)[32 + lane];
    float4 b0 = ((const float4*)b)[lane], b1 = ((const float4*)b)[32 + lane];
    float4 o0 = make_float4(d0*inv*w0.x + b0.x, d1*inv*w0.y + b0.y,
                            d2*inv*w0.z + b0.z, d3*inv*w0.w + b0.w);
    float4 o1 = make_float4(d4*inv*w1.x + b1.x, d5*inv*w1.y + b1.y,
                            d6*inv*w1.z + b1.z, d7*inv*w1.w + b1.w);
    size_t base = (size_t)row * DD;
    uint32_t ha, hb, la, lb;
    split4(o0, ha, hb, la, lb);
    *(uint2*)(g_xn_hi + base + lane*4) = make_uint2(ha, hb);
    *(uint2*)(g_xn_lo + base + lane*4) = make_uint2(la, lb);
    split4(o1, ha, hb, la, lb);
    *(uint2*)(g_xn_hi + base + 128 + lane*4) = make_uint2(ha, hb);
    *(uint2*)(g_xn_lo + base + 128 + lane*4) = make_uint2(la, lb);
}

// ---------------- weight transpose + bf16 split ----------------
__global__ __launch_bounds__(256) void wconv_kernel(
    const float* __restrict__ wq, const float* __restrict__ wk,
    const float* __restrict__ wv, const float* __restrict__ wo) {
    int n = blockIdx.x, z = blockIdx.y, k = threadIdx.x;
    const float* w = (z == 0) ? wq : (z == 1) ? wk : (z == 2) ? wv : wo;
    float v = w[(size_t)k * DD + n];
    __nv_bfloat16 h = __float2bfloat16(v);
    __nv_bfloat16 l = __float2bfloat16(v - __bfloat162float(h));
    size_t o = (size_t)z * DD * DD + (size_t)n * DD + k;
    g_wt_hi[o] = h;
    g_wt_lo[o] = l;
}

// ================= GEMM smem layout (64x128 block tile) =================
#define G2_ALO 9216
#define G2_BHI 18432
#define G2_BLO 36864
#define G2_SMEM 55296

#define GEMM_MMA_PHASE16()                                                               \
    {                                                                                    \
        _Pragma("unroll")                                                                \
        for (int kt = 0; kt < 4; kt++) {                                                 \
            uint32_t ko = (uint32_t)(kt * 32);                                           \
            uint32_t ah[4], al[4];                                                       \
            ldsm4(aB + ko,          ah[0], ah[1], ah[2], ah[3]);                         \
            ldsm4(aB + G2_ALO + ko, al[0], al[1], al[2], al[3]);                         \
            _Pragma("unroll")                                                            \
            for (int jp = 0; jp < 4; jp++) {                                             \
                uint32_t bh[4], bl[4];                                                   \
                ldsm4(bB + jp * 2304 + ko,         bh[0], bh[1], bh[2], bh[3]);          \
                ldsm4(bB + 18432 + jp * 2304 + ko, bl[0], bl[1], bl[2], bl[3]);          \
                mma_bf16(c[2*jp],   ah[0], ah[1], ah[2], ah[3], bh[0], bh[1]);           \
                mma_bf16(c[2*jp],   ah[0], ah[1], ah[2], ah[3], bl[0], bl[1]);           \
                mma_bf16(c[2*jp],   al[0], al[1], al[2], al[3], bh[0], bh[1]);           \
                mma_bf16(c[2*jp+1], ah[0], ah[1], ah[2], ah[3], bh[2], bh[3]);           \
                mma_bf16(c[2*jp+1], ah[0], ah[1], ah[2], ah[3], bl[2], bl[3]);           \
                mma_bf16(c[2*jp+1], al[0], al[1], al[2], al[3], bh[2], bh[3]);           \
            }                                                                            \
        }                                                                                \
    }

// ---------------- QKV projection (HMMA, 64x128 tile, occ-3, mask-skipped) ----------------
__global__ __launch_bounds__(256, 3) void qkv_mma_kernel(
    const float* __restrict__ bq, const float* __restrict__ bk, const float* __restrict__ bv,
    const float* __restrict__ masks) {
    extern __shared__ char sm[];
    uint32_t sbu = smem_u32(sm);
    int tid = threadIdx.x, lane = tid & 31, wid = tid >> 5;
    int g = lane >> 2, tg = lane & 3;
    int wm = wid & 3, wn = wid >> 2;
    int z = blockIdx.x >> 1;
    size_t n0 = (size_t)(blockIdx.x & 1) * 128;
    size_t m0 = (size_t)blockIdx.y * 64;
    const float* bias = (z == 0) ? bq : (z == 1) ? bk : bv;
    __nv_bfloat16* oh = (z == 0) ? g_q_hi : (z == 1) ? g_k_hi : g_v_hi;
    __nv_bfloat16* ol = (z == 0) ? g_q_lo : (z == 1) ? g_k_lo : g_v_lo;
    const __nv_bfloat16* Bh = g_wt_hi + (size_t)z * DD * DD;
    const __nv_bfloat16* Bl = g_wt_lo + (size_t)z * DD * DD;
    float scale = (z == 0) ? 0.125f : 1.0f;

    bool act = masks[m0 + wm * 16] > 0.f;

    uint32_t aoff = (uint32_t)(((lane & 15) * 72 + (lane >> 4) * 8) * 2);
    uint32_t boff = (uint32_t)((((lane & 7) + ((lane >> 4) << 3)) * 72 + (lane & 8)) * 2);
    uint32_t aB = sbu + aoff + (uint32_t)(wm * 16) * 144;
    uint32_t bB = sbu + G2_BHI + boff + (uint32_t)(wn * 64) * 144;

    float c[8][4] = {};
    for (int kc = 0; kc < 4; kc++) {
        __syncthreads();
        #pragma unroll
        for (int it = 0; it < 2; it++) {
            int i = tid + it * 256;
            int row = i >> 3, sg = i & 7;
            if (masks[m0 + (row & ~15)] > 0.f) {
                uint32_t so = (uint32_t)((row * 72 + sg * 8) * 2);
                size_t ga = (size_t)(m0 + row) * DD + kc * 64 + sg * 8;
                *(uint4*)(sm + so)          = *(const uint4*)(g_xn_hi + ga);
                *(uint4*)(sm + G2_ALO + so) = *(const uint4*)(g_xn_lo + ga);
            }
        }
        #pragma unroll
        for (int it = 0; it < 4; it++) {
            int i = tid + it * 256;
            int row = i >> 3, sg = i & 7;
            uint32_t so = (uint32_t)((row * 72 + sg * 8) * 2);
            size_t gb = (size_t)(n0 + row) * DD + kc * 64 + sg * 8;
            *(uint4*)(sm + G2_BHI + so) = *(const uint4*)(Bh + gb);
            *(uint4*)(sm + G2_BLO + so) = *(const uint4*)(Bl + gb);
        }
        __syncthreads();
        if (act) GEMM_MMA_PHASE16();
    }

    if (act) {
        int rA = (int)m0 + wm * 16 + g;
        int rB = rA + 8;
        #pragma unroll
        for (int ni = 0; ni < 8; ni++) {
            int n = (int)n0 + wn * 64 + ni * 8 + tg * 2;
            float b0v = bias[n], b1v = bias[n + 1];
            float v0 = (c[ni][0] + b0v) * scale;
            float v1 = (c[ni][1] + b1v) * scale;
            float v2 = (c[ni][2] + b0v) * scale;
            float v3 = (c[ni][3] + b1v) * scale;
            *(uint32_t*)(oh + (size_t)rA * DD + n) = packbf(v0, v1);
            *(uint32_t*)(ol + (size_t)rA * DD + n) = packbf(bflo(v0), bflo(v1));
            *(uint32_t*)(oh + (size_t)rB * DD + n) = packbf(v2, v3);
            *(uint32_t*)(ol + (size_t)rB * DD + n) = packbf(bflo(v2), bflo(v3));
        }
    }
}

// ---------------- output projection + residual + mask (HMMA, fp32 ctx A) ----------------
__global__ __launch_bounds__(256, 3) void out_mma_kernel(
    const float* __restrict__ bo, const float* __restrict__ nf,
    const float* __restrict__ masks, float* __restrict__ out) {
    extern __shared__ char sm[];
    uint32_t sbu = smem_u32(sm);
    int tid = threadIdx.x, lane = tid & 31, wid = tid >> 5;
    int g = lane >> 2, tg = lane & 3;
    int wm = wid & 3, wn = wid >> 2;
    size_t m0 = (size_t)blockIdx.x * 64, n0 = (size_t)blockIdx.y * 128;
    const __nv_bfloat16* Bh = g_wt_hi + (size_t)3 * DD * DD;
    const __nv_bfloat16* Bl = g_wt_lo + (size_t)3 * DD * DD;

    bool act = masks[m0 + wm * 16] > 0.f;

    uint32_t aoff = (uint32_t)(((lane & 15) * 72 + (lane >> 4) * 8) * 2);
    uint32_t boff = (uint32_t)((((lane & 7) + ((lane >> 4) << 3)) * 72 + (lane & 8)) * 2);
    uint32_t aB = sbu + aoff + (uint32_t)(wm * 16) * 144;
    uint32_t bB = sbu + G2_BHI + boff + (uint32_t)(wn * 64) * 144;

    float c[8][4] = {};
    for (int kc = 0; kc < 4; kc++) {
        __syncthreads();
        #pragma unroll
        for (int it = 0; it < 2; it++) {
            int i = tid + it * 256;
            int row = i >> 3, sg = i & 7;
            if (masks[m0 + (row & ~15)] > 0.f) {
                uint32_t so = (uint32_t)((row * 72 + sg * 8) * 2);
                size_t ga = (size_t)(m0 + row) * DD + kc * 64 + sg * 8;
                float4 f0 = *(const float4*)(g_ctx + ga);
                float4 f1 = *(const float4*)(g_ctx + ga + 4);
                uint32_t ha, hb, la, lb, hc, hd, lc, ld;
                split4(f0, ha, hb, la, lb);
                split4(f1, hc, hd, lc, ld);
                *(uint4*)(sm + so)          = make_uint4(ha, hb, hc, hd);
                *(uint4*)(sm + G2_ALO + so) = make_uint4(la, lb, lc, ld);
            }
        }
        #pragma unroll
        for (int it = 0; it < 4; it++) {
            int i = tid + it * 256;
            int row = i >> 3, sg = i & 7;
            uint32_t so = (uint32_t)((row * 72 + sg * 8) * 2);
            size_t gb = (size_t)(n0 + row) * DD + kc * 64 + sg * 8;
            *(uint4*)(sm + G2_BHI + so) = *(const uint4*)(Bh + gb);
            *(uint4*)(sm + G2_BLO + so) = *(const uint4*)(Bl + gb);
        }
        __syncthreads();
        if (act) GEMM_MMA_PHASE16();
    }

    {
        int rA = (int)m0 + wm * 16 + g;
        int rB = rA + 8;
        float mkA = masks[rA], mkB = masks[rB];
        #pragma unroll
        for (int ni = 0; ni < 8; ni++) {
            int n = (int)n0 + wn * 64 + ni * 8 + tg * 2;
            float b0v = bo[n], b1v = bo[n + 1];
            float2 resA = *(const float2*)(nf + (size_t)rA * DD + n);
            float2 resB = *(const float2*)(nf + (size_t)rB * DD + n);
            float2 oA = make_float2((c[ni][0] + b0v + resA.x) * mkA,
                                    (c[ni][1] + b1v + resA.y) * mkA);
            float2 oB = make_float2((c[ni][2] + b0v + resB.x) * mkB,
                                    (c[ni][3] + b1v + resB.y) * mkB);
            *(float2*)(out + (size_t)rA * DD + n) = oA;
            *(float2*)(out + (size_t)rB * DD + n) = oB;
        }
    }
}

// ---------------- CSR-by-dst attention: one block per (dst, head) ----------------
// k/v staged ONCE per block; edge loop has NO barriers (smem read-only after stage).
#define A_KH 0
#define A_KL 9216
#define A_VH 18432
#define A_VL 27648
#define A_KM 36864
#define A_SMEM 37120

__global__ __launch_bounds__(128, 4) void attn_dst_kernel(
    const float* __restrict__ etw, const float* __restrict__ masks) {
    extern __shared__ char sm[];
    uint32_t sbu = smem_u32(sm);
    float* kmv = (float*)(sm + A_KM);

    int dnode = blockIdx.x >> 2;
    int h = blockIdx.x & 3;
    int e0 = g_off[dnode], e1 = g_off[dnode + 1];
    if (e0 == e1) return;

    int tid = threadIdx.x, lane = tid & 31, wid = tid >> 5;
    int g = lane >> 2, tg = lane & 3;
    int r0 = wid * 16;

    // dst-side mask & lengths (block-invariant)
    float md0 = masks[(size_t)dnode * SS + lane], md1 = masks[(size_t)dnode * SS + 32 + lane];
    int len_dst = __popc(__ballot_sync(0xffffffffu, md0 > 0.f)) +
                  __popc(__ballot_sync(0xffffffffu, md1 > 0.f));
    int lk = (len_dst + 15) & ~15;
    int jpmax = (((len_dst + 7) >> 3) + 1) >> 1;
    int ktmax = (len_dst + 15) >> 4;

    // ---- stage k/v hi/lo tiles once ----
    size_t kbase = ((size_t)dnode * SS) * DD + h * HDIM;
    for (int i = tid; i < 512; i += 128) {
        int row = i >> 3, seg = i & 7;
        if (row < lk) {
            int so = (row * 72 + seg * 8) * 2;
            size_t go = (size_t)row * DD + seg * 8;
            *(uint4*)(sm + A_KH + so) = *(const uint4*)(g_k_hi + kbase + go);
            *(uint4*)(sm + A_KL + so) = *(const uint4*)(g_k_lo + kbase + go);
            *(uint4*)(sm + A_VH + so) = *(const uint4*)(g_v_hi + kbase + go);
            *(uint4*)(sm + A_VL + so) = *(const uint4*)(g_v_lo + kbase + go);
        }
    }
    if (tid < 32) { kmv[lane] = md0; kmv[32 + lane] = md1; }
    __syncthreads();   // the ONLY block barrier

    uint32_t boff = (uint32_t)((((lane & 7) + ((lane >> 4) << 3)) * 72 + (lane & 8)) * 2);
    uint32_t voff = (uint32_t)((lane & 15) * 144 + (lane >> 4) * 16);
    uint32_t kBH = sbu + A_KH + boff;
    uint32_t kBL = kBH + (A_KL - A_KH);
    uint32_t vBH = sbu + A_VH + voff;
    uint32_t vBL = vBH + (A_VL - A_VH);

    // key mask regs (block-invariant)
    float kmr[8][2];
    #pragma unroll
    for (int jn = 0; jn < 8; jn++) {
        int col = jn * 8 + tg * 2;
        kmr[jn][0] = kmv[col];
        kmr[jn][1] = kmv[col + 1];
    }

    // ---- edge loop: no barriers; warps proceed independently ----
    for (int idx = e0; idx < e1; idx++) {
        int e   = g_elist[idx];
        int src = g_srcv[e];
        int tt  = g_ettv[e];

        // src length (warp-uniform)
        float ms0 = masks[(size_t)src * SS + lane], ms1 = masks[(size_t)src * SS + 32 + lane];
        int len_src = __popc(__ballot_sync(0xffffffffu, ms0 > 0.f)) +
                      __popc(__ballot_sync(0xffffffffu, ms1 > 0.f));
        if (r0 >= len_src) continue;

        float xw = etw[tt - 1];
        float sp = (xw > 20.f) ? xw : log1pf(__expf(xw));
        float ew = fminf(fmaxf(sp, 1e-6f), 1e6f);

        // q A-fragments direct from global
        uint32_t qh[4][4], ql[4][4];
        {
            size_t qbase = ((size_t)src * SS) * DD + h * HDIM;
            const __nv_bfloat16* qhp = g_q_hi + qbase + (size_t)(r0 + g) * DD + tg * 2;
            const __nv_bfloat16* qlp = g_q_lo + qbase + (size_t)(r0 + g) * DD + tg * 2;
            #pragma unroll
            for (int kt = 0; kt < 4; kt++) {
                qh[kt][0] = *(const uint32_t*)(qhp + kt * 16);
                qh[kt][1] = *(const uint32_t*)(qhp + 8 * DD + kt * 16);
                qh[kt][2] = *(const uint32_t*)(qhp + kt * 16 + 8);
                qh[kt][3] = *(const uint32_t*)(qhp + 8 * DD + kt * 16 + 8);
                ql[kt][0] = *(const uint32_t*)(qlp + kt * 16);
                ql[kt][1] = *(const uint32_t*)(qlp + 8 * DD + kt * 16);
                ql[kt][2] = *(const uint32_t*)(qlp + kt * 16 + 8);
                ql[kt][3] = *(const uint32_t*)(qlp + 8 * DD + kt * 16 + 8);
            }
        }

        // scores = (q/8) @ k^T
        float sc[8][4] = {};
        #pragma unroll
        for (int kt = 0; kt < 4; kt++) {
            uint32_t ko = (uint32_t)(kt * 32);
            for (int jp = 0; jp < jpmax; jp++) {
                uint32_t bh[4], bl[4];
                ldsm4(kBH + jp * 2304 + ko, bh[0], bh[1], bh[2], bh[3]);
                ldsm4(kBL + jp * 2304 + ko, bl[0], bl[1], bl[2], bl[3]);
                mma_bf16(sc[2*jp],   qh[kt][0], qh[kt][1], qh[kt][2], qh[kt][3], bh[0], bh[1]);
                mma_bf16(sc[2*jp],   qh[kt][0], qh[kt][1], qh[kt][2], qh[kt][3], bl[0], bl[1]);
                mma_bf16(sc[2*jp],   ql[kt][0], ql[kt][1], ql[kt][2], ql[kt][3], bh[0], bh[1]);
                mma_bf16(sc[2*jp+1], qh[kt][0], qh[kt][1], qh[kt][2], qh[kt][3], bh[2], bh[3]);
                mma_bf16(sc[2*jp+1], qh[kt][0], qh[kt][1], qh[kt][2], qh[kt][3], bl[2], bl[3]);
                mma_bf16(sc[2*jp+1], ql[kt][0], ql[kt][1], ql[kt][2], ql[kt][3], bh[2], bh[3]);
            }
        }

        // bias + key mask + softmax
        #pragma unroll
        for (int jn = 0; jn < 8; jn++) {
            sc[jn][0] = (kmr[jn][0] > 0.f) ? sc[jn][0] + ew : -1e30f;
            sc[jn][1] = (kmr[jn][1] > 0.f) ? sc[jn][1] + ew : -1e30f;
            sc[jn][2] = (kmr[jn][0] > 0.f) ? sc[jn][2] + ew : -1e30f;
            sc[jn][3] = (kmr[jn][1] > 0.f) ? sc[jn][3] + ew : -1e30f;
        }
        float mA = -1e30f, mB = -1e30f;
        #pragma unroll
        for (int jn = 0; jn < 8; jn++) {
            mA = fmaxf(mA, fmaxf(sc[jn][0], sc[jn][1]));
            mB = fmaxf(mB, fmaxf(sc[jn][2], sc[jn][3]));
        }
        mA = fmaxf(mA, __shfl_xor_sync(0xffffffffu, mA, 1));
        mA = fmaxf(mA, __shfl_xor_sync(0xffffffffu, mA, 2));
        mB = fmaxf(mB, __shfl_xor_sync(0xffffffffu, mB, 1));
        mB = fmaxf(mB, __shfl_xor_sync(0xffffffffu, mB, 2));
        float sA = 0.f, sB = 0.f;
        #pragma unroll
        for (int jn = 0; jn < 8; jn++) {
            sc[jn][0] = __expf(sc[jn][0] - mA); sA += sc[jn][0];
            sc[jn][1] = __expf(sc[jn][1] - mA); sA += sc[jn][1];
            sc[jn][2] = __expf(sc[jn][2] - mB); sB += sc[jn][2];
            sc[jn][3] = __expf(sc[jn][3] - mB); sB += sc[jn][3];
        }
        sA += __shfl_xor_sync(0xffffffffu, sA, 1);
        sA += __shfl_xor_sync(0xffffffffu, sA, 2);
        sB += __shfl_xor_sync(0xffffffffu, sB, 1);
        sB += __shfl_xor_sync(0xffffffffu, sB, 2);
        float iA = 1.0f / sA, iB = 1.0f / sB;
        #pragma unroll
        for (int jn = 0; jn < 8; jn++) {
            sc[jn][0] *= iA * kmr[jn][0];
            sc[jn][1] *= iA * kmr[jn][1];
            sc[jn][2] *= iB * kmr[jn][0];
            sc[jn][3] *= iB * kmr[jn][1];
        }

        // repack P, hi/lo
        uint32_t phi[4][4], plo[4][4];
        #pragma unroll
        for (int kt = 0; kt < 4; kt++) {
            int j0 = 2 * kt, j1 = 2 * kt + 1;
            phi[kt][0] = packbf(sc[j0][0], sc[j0][1]);
            phi[kt][1] = packbf(sc[j0][2], sc[j0][3]);
            phi[kt][2] = packbf(sc[j1][0], sc[j1][1]);
            phi[kt][3] = packbf(sc[j1][2], sc[j1][3]);
            plo[kt][0] = packbf(bflo(sc[j0][0]), bflo(sc[j0][1]));
            plo[kt][1] = packbf(bflo(sc[j0][2]), bflo(sc[j0][3]));
            plo[kt][2] = packbf(bflo(sc[j1][0]), bflo(sc[j1][1]));
            plo[kt][3] = packbf(bflo(sc[j1][2]), bflo(sc[j1][3]));
        }

        // ctx = P @ V
        float o4[8][4] = {};
        for (int kt = 0; kt < ktmax; kt++) {
            uint32_t ko = (uint32_t)(kt * 2304);
            #pragma unroll
            for (int jp = 0; jp < 4; jp++) {
                uint32_t bh[4], bl[4];
                ldsm4t(vBH + ko + jp * 32, bh[0], bh[1], bh[2], bh[3]);
                ldsm4t(vBL + ko + jp * 32, bl[0], bl[1], bl[2], bl[3]);
                mma_bf16(o4[2*jp],   phi[kt][0], phi[kt][1], phi[kt][2], phi[kt][3], bh[0], bh[1]);
                mma_bf16(o4[2*jp],   phi[kt][0], phi[kt][1], phi[kt][2], phi[kt][3], bl[0], bl[1]);
                mma_bf16(o4[2*jp],   plo[kt][0], plo[kt][1], plo[kt][2], plo[kt][3], bh[0], bh[1]);
                mma_bf16(o4[2*jp+1], phi[kt][0], phi[kt][1], phi[kt][2], phi[kt][3], bh[2], bh[3]);
                mma_bf16(o4[2*jp+1], phi[kt][0], phi[kt][1], phi[kt][2], phi[kt][3], bl[2], bl[3]);
                mma_bf16(o4[2*jp+1], plo[kt][0], plo[kt][1], plo[kt][2], plo[kt][3], bh[2], bh[3]);
            }
        }

        // scatter-add with query mask
        int rowA = r0 + g, rowB = r0 + g + 8;
        float qmA = masks[(size_t)src * SS + rowA];
        float qmB = masks[(size_t)src * SS + rowB];
        float* baseA = g_ctx + ((size_t)src * SS + rowA) * DD + h * HDIM;
        float* baseB = g_ctx + ((size_t)src * SS + rowB) * DD + h * HDIM;
        #pragma unroll
        for (int jn = 0; jn < 8; jn++) {
            int col = jn * 8 + tg * 2;
            if (qmA > 0.f) {
                atomicAdd(baseA + col,     o4[jn][0] * qmA);
                atomicAdd(baseA + col + 1, o4[jn][1] * qmA);
            }
            if (qmB > 0.f) {
                atomicAdd(baseB + col,     o4[jn][2] * qmB);
                atomicAdd(baseB + col + 1, o4[jn][3] * qmB);
            }
        }
    }
}

extern "C" void kernel_launch(void* const* d_in, const int* in_sizes, int n_in,
                              void* d_out, int out_size) {
    const float* nf    = (const float*)d_in[0];
    const float* masks = (const float*)d_in[1];
    const float* lnw   = (const float*)d_in[2];
    const float* lnb   = (const float*)d_in[3];
    const float* wq    = (const float*)d_in[4];
    const float* bq    = (const float*)d_in[5];
    const float* wk    = (const float*)d_in[6];
    const float* bk    = (const float*)d_in[7];
    const float* wv    = (const float*)d_in[8];
    const float* bv    = (const float*)d_in[9];
    const float* wo    = (const float*)d_in[10];
    const float* bo    = (const float*)d_in[11];
    const float* etw   = (const float*)d_in[12];
    const long long* ei = (const long long*)d_in[13];
    const long long* et = (const long long*)d_in[14];
    float* out = (float*)d_out;

    cudaFuncSetAttribute(qkv_mma_kernel, cudaFuncAttributeMaxDynamicSharedMemorySize, G2_SMEM);
    cudaFuncSetAttribute(out_mma_kernel, cudaFuncAttributeMaxDynamicSharedMemorySize, G2_SMEM);
    cudaFuncSetAttribute(attn_dst_kernel, cudaFuncAttributeMaxDynamicSharedMemorySize, A_SMEM);

    edges0_kernel<<<NN / 256, 256>>>();
    edges1_kernel<<<EE / 256, 256>>>(ei, et);
    edges2_kernel<<<1, 1024>>>();
    zero_ctx_kernel<<<ROWS * 4 / 256, 256>>>(masks);
    ln_kernel<<<ROWS / 8, 256>>>(nf, lnw, lnb, masks);
    wconv_kernel<<<dim3(DD, 4), 256>>>(wq, wk, wv, wo);
    qkv_mma_kernel<<<dim3(6, ROWS / 64), 256, G2_SMEM>>>(bq, bk, bv, masks);
    attn_dst_kernel<<<NN * HH, 128, A_SMEM>>>(etw, masks);
    out_mma_kernel<<<dim3(ROWS / 64, DD / 128), 256, G2_SMEM>>>(bo, nf, masks, out);
}

// round 17
// speedup vs baseline: 1.2367x; 1.2367x over previous
#include <cuda_runtime.h>
#include <cuda_bf16.h>
#include <math.h>
#include <stdint.h>

#define NN   1024
#define SS   64
#define DD   256
#define HH   4
#define HDIM 64
#define EE   4096
#define ROWS (NN*SS)   // 65536

// -------- scratch (allocation-free: device globals) --------
__device__ __nv_bfloat16 g_xn_hi[ROWS*DD];
__device__ __nv_bfloat16 g_xn_lo[ROWS*DD];
__device__ __nv_bfloat16 g_q_hi [ROWS*DD];   // pre-scaled by 1/8
__device__ __nv_bfloat16 g_q_lo [ROWS*DD];
__device__ __nv_bfloat16 g_k_hi [ROWS*DD];
__device__ __nv_bfloat16 g_k_lo [ROWS*DD];
__device__ __nv_bfloat16 g_v_hi [ROWS*DD];
__device__ __nv_bfloat16 g_v_lo [ROWS*DD];
__device__ float g_ctx[ROWS*DD];
__device__ __nv_bfloat16 g_wt_hi[4*DD*DD];   // transposed weights [n][k] (q,k,v,o)
__device__ __nv_bfloat16 g_wt_lo[4*DD*DD];

// ================= MMA / ldmatrix helpers =================
__device__ __forceinline__ void mma_bf16(float c[4],
    uint32_t a0, uint32_t a1, uint32_t a2, uint32_t a3, uint32_t b0, uint32_t b1) {
    asm volatile(
        "mma.sync.aligned.m16n8k16.row.col.f32.bf16.bf16.f32 "
        "{%0,%1,%2,%3}, {%4,%5,%6,%7}, {%8,%9}, {%0,%1,%2,%3};"
        : "+f"(c[0]), "+f"(c[1]), "+f"(c[2]), "+f"(c[3])
        : "r"(a0), "r"(a1), "r"(a2), "r"(a3), "r"(b0), "r"(b1));
}
__device__ __forceinline__ void ldsm4(uint32_t a, uint32_t& r0, uint32_t& r1,
                                      uint32_t& r2, uint32_t& r3) {
    asm volatile("ldmatrix.sync.aligned.m8n8.x4.shared.b16 {%0,%1,%2,%3}, [%4];"
        : "=r"(r0), "=r"(r1), "=r"(r2), "=r"(r3) : "r"(a));
}
__device__ __forceinline__ void ldsm4t(uint32_t a, uint32_t& r0, uint32_t& r1,
                                       uint32_t& r2, uint32_t& r3) {
    asm volatile("ldmatrix.sync.aligned.m8n8.x4.trans.shared.b16 {%0,%1,%2,%3}, [%4];"
        : "=r"(r0), "=r"(r1), "=r"(r2), "=r"(r3) : "r"(a));
}
__device__ __forceinline__ uint32_t smem_u32(const void* p) {
    uint32_t r;
    asm("{ .reg .u64 t; cvta.to.shared.u64 t, %1; cvt.u32.u64 %0, t; }" : "=r"(r) : "l"(p));
    return r;
}
__device__ __forceinline__ uint32_t packbf(float x, float y) {
    __nv_bfloat162 t = __floats2bfloat162_rn(x, y);
    return *(uint32_t*)&t;
}
__device__ __forceinline__ float bflo(float x) {
    return x - __bfloat162float(__float2bfloat16(x));
}
__device__ __forceinline__ void split4(float4 v, uint32_t& hi2a, uint32_t& hi2b,
                                       uint32_t& lo2a, uint32_t& lo2b) {
    hi2a = packbf(v.x, v.y); hi2b = packbf(v.z, v.w);
    lo2a = packbf(bflo(v.x), bflo(v.y)); lo2b = packbf(bflo(v.z), bflo(v.w));
}

// ---------------- zero the context accumulator (mask-skipped, 1 float4/thread) ----------------
__global__ __launch_bounds__(256) void zero_ctx_kernel(const float* __restrict__ masks) {
    int gid = blockIdx.x * 256 + threadIdx.x;   // 0 .. ROWS*DD/4-1
    int row = gid >> 6;                          // 64 float4 per row
    if (masks[row & ~15] <= 0.f) return;
    ((float4*)g_ctx)[gid] = make_float4(0.f, 0.f, 0.f, 0.f);
}

// ---------------- LayerNorm -> bf16 hi/lo split (mask-skipped) ----------------
__global__ __launch_bounds__(256) void ln_kernel(
    const float* __restrict__ x, const float* __restrict__ w, const float* __restrict__ b,
    const float* __restrict__ masks) {
    int row  = blockIdx.x * 8 + (threadIdx.x >> 5);
    int lane = threadIdx.x & 31;
    if (masks[row & ~15] <= 0.f) return;
    const float4* xr = (const float4*)(x + (size_t)row * DD);
    float4 v0 = xr[lane];
    float4 v1 = xr[32 + lane];
    float s = v0.x + v0.y + v0.z + v0.w + v1.x + v1.y + v1.z + v1.w;
    #pragma unroll
    for (int o = 16; o; o >>= 1) s += __shfl_xor_sync(0xffffffffu, s, o);
    float mu = s * (1.0f / DD);
    float d0 = v0.x - mu, d1 = v0.y - mu, d2 = v0.z - mu, d3 = v0.w - mu;
    float d4 = v1.x - mu, d5 = v1.y - mu, d6 = v1.z - mu, d7 = v1.w - mu;
    float ss = d0*d0 + d1*d1 + d2*d2 + d3*d3 + d4*d4 + d5*d5 + d6*d6 + d7*d7;
    #pragma unroll
    for (int o = 16; o; o >>= 1) ss += __shfl_xor_sync(0xffffffffu, ss, o);
    float inv = rsqrtf(ss * (1.0f / DD) + 1e-5f);
    float4 w0 = ((const float4*)w)[lane], w1 = ((const float4*)w)[32 + lane];
    float4 b0 = ((const float4*)b)[lane], b1 = ((const float4*)b)[32 + lane];
    float4 o0 = make_float4(d0*inv*w0.x + b0.x, d1*inv*w0.y + b0.y,
                            d2*inv*w0.z + b0.z, d3*inv*w0.w + b0.w);
    float4 o1 = make_float4(d4*inv*w1.x + b1.x, d5*inv*w1.y + b1.y,
                            d6*inv*w1.z + b1.z, d7*inv*w1.w + b1.w);
    size_t base = (size_t)row * DD;
    uint32_t ha, hb, la, lb;
    split4(o0, ha, hb, la, lb);
    *(uint2*)(g_xn_hi + base + lane*4) = make_uint2(ha, hb);
    *(uint2*)(g_xn_lo + base + lane*4) = make_uint2(la, lb);
    split4(o1, ha, hb, la, lb);
    *(uint2*)(g_xn_hi + base + 128 + lane*4) = make_uint2(ha, hb);
    *(uint2*)(g_xn_lo + base + 128 + lane*4) = make_uint2(la, lb);
}

// ---------------- weight transpose + bf16 split ----------------
__global__ __launch_bounds__(256) void wconv_kernel(
    const float* __restrict__ wq, const float* __restrict__ wk,
    const float* __restrict__ wv, const float* __restrict__ wo) {
    int n = blockIdx.x, z = blockIdx.y, k = threadIdx.x;
    const float* w = (z == 0) ? wq : (z == 1) ? wk : (z == 2) ? wv : wo;
    float v = w[(size_t)k * DD + n];
    __nv_bfloat16 h = __float2bfloat16(v);
    __nv_bfloat16 l = __float2bfloat16(v - __bfloat162float(h));
    size_t o = (size_t)z * DD * DD + (size_t)n * DD + k;
    g_wt_hi[o] = h;
    g_wt_lo[o] = l;
}

// ================= GEMM smem layout (64x128 block tile) =================
#define G2_ALO 9216
#define G2_BHI 18432
#define G2_BLO 36864
#define G2_SMEM 55296

#define GEMM_MMA_PHASE16()                                                               \
    {                                                                                    \
        _Pragma("unroll")                                                                \
        for (int kt = 0; kt < 4; kt++) {                                                 \
            uint32_t ko = (uint32_t)(kt * 32);                                           \
            uint32_t ah[4], al[4];                                                       \
            ldsm4(aB + ko,          ah[0], ah[1], ah[2], ah[3]);                         \
            ldsm4(aB + G2_ALO + ko, al[0], al[1], al[2], al[3]);                         \
            _Pragma("unroll")                                                            \
            for (int jp = 0; jp < 4; jp++) {                                             \
                uint32_t bh[4], bl[4];                                                   \
                ldsm4(bB + jp * 2304 + ko,         bh[0], bh[1], bh[2], bh[3]);          \
                ldsm4(bB + 18432 + jp * 2304 + ko, bl[0], bl[1], bl[2], bl[3]);          \
                mma_bf16(c[2*jp],   ah[0], ah[1], ah[2], ah[3], bh[0], bh[1]);           \
                mma_bf16(c[2*jp],   ah[0], ah[1], ah[2], ah[3], bl[0], bl[1]);           \
                mma_bf16(c[2*jp],   al[0], al[1], al[2], al[3], bh[0], bh[1]);           \
                mma_bf16(c[2*jp+1], ah[0], ah[1], ah[2], ah[3], bh[2], bh[3]);           \
                mma_bf16(c[2*jp+1], ah[0], ah[1], ah[2], ah[3], bl[2], bl[3]);           \
                mma_bf16(c[2*jp+1], al[0], al[1], al[2], al[3], bh[2], bh[3]);           \
            }                                                                            \
        }                                                                                \
    }

// ---------------- QKV projection (HMMA, 64x128 tile, occ-3, mask-skipped) ----------------
__global__ __launch_bounds__(256, 3) void qkv_mma_kernel(
    const float* __restrict__ bq, const float* __restrict__ bk, const float* __restrict__ bv,
    const float* __restrict__ masks) {
    extern __shared__ char sm[];
    uint32_t sbu = smem_u32(sm);
    int tid = threadIdx.x, lane = tid & 31, wid = tid >> 5;
    int g = lane >> 2, tg = lane & 3;
    int wm = wid & 3, wn = wid >> 2;
    int z = blockIdx.x >> 1;
    size_t n0 = (size_t)(blockIdx.x & 1) * 128;
    size_t m0 = (size_t)blockIdx.y * 64;
    const float* bias = (z == 0) ? bq : (z == 1) ? bk : bv;
    __nv_bfloat16* oh = (z == 0) ? g_q_hi : (z == 1) ? g_k_hi : g_v_hi;
    __nv_bfloat16* ol = (z == 0) ? g_q_lo : (z == 1) ? g_k_lo : g_v_lo;
    const __nv_bfloat16* Bh = g_wt_hi + (size_t)z * DD * DD;
    const __nv_bfloat16* Bl = g_wt_lo + (size_t)z * DD * DD;
    float scale = (z == 0) ? 0.125f : 1.0f;

    bool act = masks[m0 + wm * 16] > 0.f;

    uint32_t aoff = (uint32_t)(((lane & 15) * 72 + (lane >> 4) * 8) * 2);
    uint32_t boff = (uint32_t)((((lane & 7) + ((lane >> 4) << 3)) * 72 + (lane & 8)) * 2);
    uint32_t aB = sbu + aoff + (uint32_t)(wm * 16) * 144;
    uint32_t bB = sbu + G2_BHI + boff + (uint32_t)(wn * 64) * 144;

    float c[8][4] = {};
    for (int kc = 0; kc < 4; kc++) {
        __syncthreads();
        #pragma unroll
        for (int it = 0; it < 2; it++) {
            int i = tid + it * 256;
            int row = i >> 3, sg = i & 7;
            if (masks[m0 + (row & ~15)] > 0.f) {
                uint32_t so = (uint32_t)((row * 72 + sg * 8) * 2);
                size_t ga = (size_t)(m0 + row) * DD + kc * 64 + sg * 8;
                *(uint4*)(sm + so)          = *(const uint4*)(g_xn_hi + ga);
                *(uint4*)(sm + G2_ALO + so) = *(const uint4*)(g_xn_lo + ga);
            }
        }
        #pragma unroll
        for (int it = 0; it < 4; it++) {
            int i = tid + it * 256;
            int row = i >> 3, sg = i & 7;
            uint32_t so = (uint32_t)((row * 72 + sg * 8) * 2);
            size_t gb = (size_t)(n0 + row) * DD + kc * 64 + sg * 8;
            *(uint4*)(sm + G2_BHI + so) = *(const uint4*)(Bh + gb);
            *(uint4*)(sm + G2_BLO + so) = *(const uint4*)(Bl + gb);
        }
        __syncthreads();
        if (act) GEMM_MMA_PHASE16();
    }

    if (act) {
        int rA = (int)m0 + wm * 16 + g;
        int rB = rA + 8;
        #pragma unroll
        for (int ni = 0; ni < 8; ni++) {
            int n = (int)n0 + wn * 64 + ni * 8 + tg * 2;
            float b0v = bias[n], b1v = bias[n + 1];
            float v0 = (c[ni][0] + b0v) * scale;
            float v1 = (c[ni][1] + b1v) * scale;
            float v2 = (c[ni][2] + b0v) * scale;
            float v3 = (c[ni][3] + b1v) * scale;
            *(uint32_t*)(oh + (size_t)rA * DD + n) = packbf(v0, v1);
            *(uint32_t*)(ol + (size_t)rA * DD + n) = packbf(bflo(v0), bflo(v1));
            *(uint32_t*)(oh + (size_t)rB * DD + n) = packbf(v2, v3);
            *(uint32_t*)(ol + (size_t)rB * DD + n) = packbf(bflo(v2), bflo(v3));
        }
    }
}

// ---------------- output projection + residual + mask (HMMA, fp32 ctx A) ----------------
__global__ __launch_bounds__(256, 3) void out_mma_kernel(
    const float* __restrict__ bo, const float* __restrict__ nf,
    const float* __restrict__ masks, float* __restrict__ out) {
    extern __shared__ char sm[];
    uint32_t sbu = smem_u32(sm);
    int tid = threadIdx.x, lane = tid & 31, wid = tid >> 5;
    int g = lane >> 2, tg = lane & 3;
    int wm = wid & 3, wn = wid >> 2;
    size_t m0 = (size_t)blockIdx.x * 64, n0 = (size_t)blockIdx.y * 128;
    const __nv_bfloat16* Bh = g_wt_hi + (size_t)3 * DD * DD;
    const __nv_bfloat16* Bl = g_wt_lo + (size_t)3 * DD * DD;

    bool act = masks[m0 + wm * 16] > 0.f;

    uint32_t aoff = (uint32_t)(((lane & 15) * 72 + (lane >> 4) * 8) * 2);
    uint32_t boff = (uint32_t)((((lane & 7) + ((lane >> 4) << 3)) * 72 + (lane & 8)) * 2);
    uint32_t aB = sbu + aoff + (uint32_t)(wm * 16) * 144;
    uint32_t bB = sbu + G2_BHI + boff + (uint32_t)(wn * 64) * 144;

    float c[8][4] = {};
    for (int kc = 0; kc < 4; kc++) {
        __syncthreads();
        #pragma unroll
        for (int it = 0; it < 2; it++) {
            int i = tid + it * 256;
            int row = i >> 3, sg = i & 7;
            if (masks[m0 + (row & ~15)] > 0.f) {
                uint32_t so = (uint32_t)((row * 72 + sg * 8) * 2);
                size_t ga = (size_t)(m0 + row) * DD + kc * 64 + sg * 8;
                float4 f0 = *(const float4*)(g_ctx + ga);
                float4 f1 = *(const float4*)(g_ctx + ga + 4);
                uint32_t ha, hb, la, lb, hc, hd, lc, ld;
                split4(f0, ha, hb, la, lb);
                split4(f1, hc, hd, lc, ld);
                *(uint4*)(sm + so)          = make_uint4(ha, hb, hc, hd);
                *(uint4*)(sm + G2_ALO + so) = make_uint4(la, lb, lc, ld);
            }
        }
        #pragma unroll
        for (int it = 0; it < 4; it++) {
            int i = tid + it * 256;
            int row = i >> 3, sg = i & 7;
            uint32_t so = (uint32_t)((row * 72 + sg * 8) * 2);
            size_t gb = (size_t)(n0 + row) * DD + kc * 64 + sg * 8;
            *(uint4*)(sm + G2_BHI + so) = *(const uint4*)(Bh + gb);
            *(uint4*)(sm + G2_BLO + so) = *(const uint4*)(Bl + gb);
        }
        __syncthreads();
        if (act) GEMM_MMA_PHASE16();
    }

    {
        int rA = (int)m0 + wm * 16 + g;
        int rB = rA + 8;
        float mkA = masks[rA], mkB = masks[rB];
        #pragma unroll
        for (int ni = 0; ni < 8; ni++) {
            int n = (int)n0 + wn * 64 + ni * 8 + tg * 2;
            float b0v = bo[n], b1v = bo[n + 1];
            float2 resA = *(const float2*)(nf + (size_t)rA * DD + n);
            float2 resB = *(const float2*)(nf + (size_t)rB * DD + n);
            float2 oA = make_float2((c[ni][0] + b0v + resA.x) * mkA,
                                    (c[ni][1] + b1v + resA.y) * mkA);
            float2 oB = make_float2((c[ni][2] + b0v + resB.x) * mkB,
                                    (c[ni][3] + b1v + resB.y) * mkB);
            *(float2*)(out + (size_t)rA * DD + n) = oA;
            *(float2*)(out + (size_t)rB * DD + n) = oB;
        }
    }
}

// ---------------- per-(edge, head) attention: q-direct + HMMA + mask skipping ----------------
#define A_KH 0
#define A_KL 9216
#define A_VH 18432
#define A_VL 27648
#define A_KM 36864
#define A_QM 37120
#define A_SMEM 37376

__global__ __launch_bounds__(128, 4) void attn_mma_kernel(
    const long long* __restrict__ ei, const long long* __restrict__ et,
    const float* __restrict__ etw, const float* __restrict__ masks) {
    extern __shared__ char sm[];
    uint32_t sbu = smem_u32(sm);
    float* kmv = (float*)(sm + A_KM);
    float* qmv = (float*)(sm + A_QM);

    int e = blockIdx.x >> 2;
    int h = blockIdx.x & 3;
    int tid = threadIdx.x, lane = tid & 31, wid = tid >> 5;
    int g = lane >> 2, tg = lane & 3;

    bool is64 = true;
    #pragma unroll
    for (int i = 0; i < 16; i++) {
        long long v = ei[i];
        if (v < 0 || v >= NN) { is64 = false; break; }
    }
    const int* ei32 = (const int*)ei;
    const int* et32 = (const int*)et;
    int src = is64 ? (int)ei[e]      : ei32[e];
    int dst = is64 ? (int)ei[EE + e] : ei32[EE + e];
    int tt  = is64 ? (int)et[e]      : et32[e];
    float xw = etw[tt - 1];
    float sp = (xw > 20.f) ? xw : log1pf(__expf(xw));
    float ew = fminf(fmaxf(sp, 1e-6f), 1e6f);

    float md0 = masks[(size_t)dst * SS + lane], md1 = masks[(size_t)dst * SS + 32 + lane];
    float ms0 = masks[(size_t)src * SS + lane], ms1 = masks[(size_t)src * SS + 32 + lane];
    int len_dst = __popc(__ballot_sync(0xffffffffu, md0 > 0.f)) +
                  __popc(__ballot_sync(0xffffffffu, md1 > 0.f));
    int len_src = __popc(__ballot_sync(0xffffffffu, ms0 > 0.f)) +
                  __popc(__ballot_sync(0xffffffffu, ms1 > 0.f));
    int lk = (len_dst + 15) & ~15;
    int jpmax = (((len_dst + 7) >> 3) + 1) >> 1;
    int ktmax = (len_dst + 15) >> 4;

    int r0 = wid * 16;
    bool wact = r0 < len_src;

    // ---- prefetch q A-fragments straight from global (no smem staging) ----
    uint32_t qh[4][4], ql[4][4];
    if (wact) {
        size_t qbase = ((size_t)src * SS) * DD + h * HDIM;
        const __nv_bfloat16* qhp = g_q_hi + qbase + (size_t)(r0 + g) * DD + tg * 2;
        const __nv_bfloat16* qlp = g_q_lo + qbase + (size_t)(r0 + g) * DD + tg * 2;
        #pragma unroll
        for (int kt = 0; kt < 4; kt++) {
            qh[kt][0] = *(const uint32_t*)(qhp + kt * 16);
            qh[kt][1] = *(const uint32_t*)(qhp + 8 * DD + kt * 16);
            qh[kt][2] = *(const uint32_t*)(qhp + kt * 16 + 8);
            qh[kt][3] = *(const uint32_t*)(qhp + 8 * DD + kt * 16 + 8);
            ql[kt][0] = *(const uint32_t*)(qlp + kt * 16);
            ql[kt][1] = *(const uint32_t*)(qlp + 8 * DD + kt * 16);
            ql[kt][2] = *(const uint32_t*)(qlp + kt * 16 + 8);
            ql[kt][3] = *(const uint32_t*)(qlp + 8 * DD + kt * 16 + 8);
        }
    }

    // ---- stage k/v hi/lo tiles (row-major) ----
    size_t kbase = ((size_t)dst * SS) * DD + h * HDIM;
    for (int i = tid; i < 512; i += 128) {
        int row = i >> 3, seg = i & 7;
        if (row < lk) {
            int so = (row * 72 + seg * 8) * 2;
            size_t go = (size_t)row * DD + seg * 8;
            *(uint4*)(sm + A_KH + so) = *(const uint4*)(g_k_hi + kbase + go);
            *(uint4*)(sm + A_KL + so) = *(const uint4*)(g_k_lo + kbase + go);
            *(uint4*)(sm + A_VH + so) = *(const uint4*)(g_v_hi + kbase + go);
            *(uint4*)(sm + A_VL + so) = *(const uint4*)(g_v_lo + kbase + go);
        }
    }
    if (tid < 32) { kmv[lane] = md0; kmv[32 + lane] = md1; }
    else if (tid < 64) { qmv[lane] = ms0; qmv[32 + lane] = ms1; }
    __syncthreads();

    if (!wact) return;

    uint32_t boff = (uint32_t)((((lane & 7) + ((lane >> 4) << 3)) * 72 + (lane & 8)) * 2);
    uint32_t voff = (uint32_t)((lane & 15) * 144 + (lane >> 4) * 16);
    uint32_t kBH = sbu + A_KH + boff;
    uint32_t kBL = kBH + (A_KL - A_KH);
    uint32_t vBH = sbu + A_VH + voff;
    uint32_t vBL = vBH + (A_VL - A_VH);

    // ---- scores = (q/8) @ k^T ----
    float sc[8][4] = {};
    #pragma unroll
    for (int kt = 0; kt < 4; kt++) {
        uint32_t ko = (uint32_t)(kt * 32);
        for (int jp = 0; jp < jpmax; jp++) {
            uint32_t bh[4], bl[4];
            ldsm4(kBH + jp * 2304 + ko, bh[0], bh[1], bh[2], bh[3]);
            ldsm4(kBL + jp * 2304 + ko, bl[0], bl[1], bl[2], bl[3]);
            mma_bf16(sc[2*jp],   qh[kt][0], qh[kt][1], qh[kt][2], qh[kt][3], bh[0], bh[1]);
            mma_bf16(sc[2*jp],   qh[kt][0], qh[kt][1], qh[kt][2], qh[kt][3], bl[0], bl[1]);
            mma_bf16(sc[2*jp],   ql[kt][0], ql[kt][1], ql[kt][2], ql[kt][3], bh[0], bh[1]);
            mma_bf16(sc[2*jp+1], qh[kt][0], qh[kt][1], qh[kt][2], qh[kt][3], bh[2], bh[3]);
            mma_bf16(sc[2*jp+1], qh[kt][0], qh[kt][1], qh[kt][2], qh[kt][3], bl[2], bl[3]);
            mma_bf16(sc[2*jp+1], ql[kt][0], ql[kt][1], ql[kt][2], ql[kt][3], bh[2], bh[3]);
        }
    }

    // ---- bias + key mask + softmax ----
    float kmr[8][2];
    #pragma unroll
    for (int jn = 0; jn < 8; jn++) {
        int col = jn * 8 + tg * 2;
        kmr[jn][0] = kmv[col];
        kmr[jn][1] = kmv[col + 1];
        sc[jn][0] = (kmr[jn][0] > 0.f) ? sc[jn][0] + ew : -1e30f;
        sc[jn][1] = (kmr[jn][1] > 0.f) ? sc[jn][1] + ew : -1e30f;
        sc[jn][2] = (kmr[jn][0] > 0.f) ? sc[jn][2] + ew : -1e30f;
        sc[jn][3] = (kmr[jn][1] > 0.f) ? sc[jn][3] + ew : -1e30f;
    }
    float mA = -1e30f, mB = -1e30f;
    #pragma unroll
    for (int jn = 0; jn < 8; jn++) {
        mA = fmaxf(mA, fmaxf(sc[jn][0], sc[jn][1]));
        mB = fmaxf(mB, fmaxf(sc[jn][2], sc[jn][3]));
    }
    mA = fmaxf(mA, __shfl_xor_sync(0xffffffffu, mA, 1));
    mA = fmaxf(mA, __shfl_xor_sync(0xffffffffu, mA, 2));
    mB = fmaxf(mB, __shfl_xor_sync(0xffffffffu, mB, 1));
    mB = fmaxf(mB, __shfl_xor_sync(0xffffffffu, mB, 2));
    float sA = 0.f, sB = 0.f;
    #pragma unroll
    for (int jn = 0; jn < 8; jn++) {
        sc[jn][0] = __expf(sc[jn][0] - mA); sA += sc[jn][0];
        sc[jn][1] = __expf(sc[jn][1] - mA); sA += sc[jn][1];
        sc[jn][2] = __expf(sc[jn][2] - mB); sB += sc[jn][2];
        sc[jn][3] = __expf(sc[jn][3] - mB); sB += sc[jn][3];
    }
    sA += __shfl_xor_sync(0xffffffffu, sA, 1);
    sA += __shfl_xor_sync(0xffffffffu, sA, 2);
    sB += __shfl_xor_sync(0xffffffffu, sB, 1);
    sB += __shfl_xor_sync(0xffffffffu, sB, 2);
    float iA = 1.0f / sA, iB = 1.0f / sB;
    #pragma unroll
    for (int jn = 0; jn < 8; jn++) {
        sc[jn][0] *= iA * kmr[jn][0];
        sc[jn][1] *= iA * kmr[jn][1];
        sc[jn][2] *= iB * kmr[jn][0];
        sc[jn][3] *= iB * kmr[jn][1];
    }

    // ---- repack P (C-frag -> A-frag), hi/lo ----
    uint32_t phi[4][4], plo[4][4];
    #pragma unroll
    for (int kt = 0; kt < 4; kt++) {
        int j0 = 2 * kt, j1 = 2 * kt + 1;
        phi[kt][0] = packbf(sc[j0][0], sc[j0][1]);
        phi[kt][1] = packbf(sc[j0][2], sc[j0][3]);
        phi[kt][2] = packbf(sc[j1][0], sc[j1][1]);
        phi[kt][3] = packbf(sc[j1][2], sc[j1][3]);
        plo[kt][0] = packbf(bflo(sc[j0][0]), bflo(sc[j0][1]));
        plo[kt][1] = packbf(bflo(sc[j0][2]), bflo(sc[j0][3]));
        plo[kt][2] = packbf(bflo(sc[j1][0]), bflo(sc[j1][1]));
        plo[kt][3] = packbf(bflo(sc[j1][2]), bflo(sc[j1][3]));
    }

    // ---- ctx = P @ V via ldmatrix.trans on row-major V ----
    float o4[8][4] = {};
    for (int kt = 0; kt < ktmax; kt++) {
        uint32_t ko = (uint32_t)(kt * 2304);
        #pragma unroll
        for (int jp = 0; jp < 4; jp++) {
            uint32_t bh[4], bl[4];
            ldsm4t(vBH + ko + jp * 32, bh[0], bh[1], bh[2], bh[3]);
            ldsm4t(vBL + ko + jp * 32, bl[0], bl[1], bl[2], bl[3]);
            mma_bf16(o4[2*jp],   phi[kt][0], phi[kt][1], phi[kt][2], phi[kt][3], bh[0], bh[1]);
            mma_bf16(o4[2*jp],   phi[kt][0], phi[kt][1], phi[kt][2], phi[kt][3], bl[0], bl[1]);
            mma_bf16(o4[2*jp],   plo[kt][0], plo[kt][1], plo[kt][2], plo[kt][3], bh[0], bh[1]);
            mma_bf16(o4[2*jp+1], phi[kt][0], phi[kt][1], phi[kt][2], phi[kt][3], bh[2], bh[3]);
            mma_bf16(o4[2*jp+1], phi[kt][0], phi[kt][1], phi[kt][2], phi[kt][3], bl[2], bl[3]);
            mma_bf16(o4[2*jp+1], plo[kt][0], plo[kt][1], plo[kt][2], plo[kt][3], bh[2], bh[3]);
        }
    }

    // ---- scatter-add into g_ctx with query mask ----
    int rowA = r0 + g, rowB = r0 + g + 8;
    float qmA = qmv[rowA], qmB = qmv[rowB];
    float* baseA = g_ctx + ((size_t)src * SS + rowA) * DD + h * HDIM;
    float* baseB = g_ctx + ((size_t)src * SS + rowB) * DD + h * HDIM;
    #pragma unroll
    for (int jn = 0; jn < 8; jn++) {
        int col = jn * 8 + tg * 2;
        if (qmA > 0.f) {
            atomicAdd(baseA + col,     o4[jn][0] * qmA);
            atomicAdd(baseA + col + 1, o4[jn][1] * qmA);
        }
        if (qmB > 0.f) {
            atomicAdd(baseB + col,     o4[jn][2] * qmB);
            atomicAdd(baseB + col + 1, o4[jn][3] * qmB);
        }
    }
}

extern "C" void kernel_launch(void* const* d_in, const int* in_sizes, int n_in,
                              void* d_out, int out_size) {
    const float* nf    = (const float*)d_in[0];
    const float* masks = (const float*)d_in[1];
    const float* lnw   = (const float*)d_in[2];
    const float* lnb   = (const float*)d_in[3];
    const float* wq    = (const float*)d_in[4];
    const float* bq    = (const float*)d_in[5];
    const float* wk    = (const float*)d_in[6];
    const float* bk    = (const float*)d_in[7];
    const float* wv    = (const float*)d_in[8];
    const float* bv    = (const float*)d_in[9];
    const float* wo    = (const float*)d_in[10];
    const float* bo    = (const float*)d_in[11];
    const float* etw   = (const float*)d_in[12];
    const long long* ei = (const long long*)d_in[13];
    const long long* et = (const long long*)d_in[14];
    float* out = (float*)d_out;

    cudaFuncSetAttribute(qkv_mma_kernel, cudaFuncAttributeMaxDynamicSharedMemorySize, G2_SMEM);
    cudaFuncSetAttribute(out_mma_kernel, cudaFuncAttributeMaxDynamicSharedMemorySize, G2_SMEM);
    cudaFuncSetAttribute(attn_mma_kernel, cudaFuncAttributeMaxDynamicSharedMemorySize, A_SMEM);

    zero_ctx_kernel<<<ROWS * DD / 4 / 256, 256>>>(masks);
    ln_kernel<<<ROWS / 8, 256>>>(nf, lnw, lnb, masks);
    wconv_kernel<<<dim3(DD, 4), 256>>>(wq, wk, wv, wo);
    qkv_mma_kernel<<<dim3(6, ROWS / 64), 256, G2_SMEM>>>(bq, bk, bv, masks);
    attn_mma_kernel<<<EE * HH, 128, A_SMEM>>>(ei, et, etw, masks);
    out_mma_kernel<<<dim3(ROWS / 64, DD / 128), 256, G2_SMEM>>>(bo, nf, masks, out);
}